// round 13
// baseline (speedup 1.0000x reference)
#include <cuda_runtime.h>

typedef unsigned long long ull;

// ----------------------------------------------------------------------------
// Clebsch-Gordan sparse product, LMAX=5, TAU=32, BATCH=32.
// R13 = R11 (M-grouped packed-f32x2 products, imm-FFMA CG accumulation, all-L
// smem image + bulk TMA stores, 8 iters/block, grid 36*32 LPT) + DOUBLE-
// BUFFERED image for pairs whose image fits twice in the 36KB region
// (sum TW <= 18): those blocks alternate image buffers per iter and use
// wait_group.read 1, fully hiding the TMA smem-read round-trip that dominated
// the light-pair blocks. Heavy pairs keep single-buffer (wait already hidden
// by their long compute).
// ----------------------------------------------------------------------------

#define LMAXV 5
#define ROWF  1579008            // output floats per batch row
#define NBLOCKS (36*32)          // pairOrder(36, slowest) * b(32)
#define IMG_F 9216               // image region: 256 * sum(2l+1, l=0..5) floats

// ---------------- packed f32x2 helpers ----------------

__device__ __forceinline__ void mul2(ull& d, ull a, ull b) {
    asm("mul.rn.f32x2 %0,%1,%2;" : "=l"(d) : "l"(a), "l"(b));
}
__device__ __forceinline__ void fma2p(ull& d, ull a, ull b, ull c) {
    asm("fma.rn.f32x2 %0,%1,%2,%3;" : "=l"(d) : "l"(a), "l"(b), "l"(c));
}
__device__ __forceinline__ void pack2(ull& d, float x, float y) {
    asm("mov.b64 %0,{%1,%2};" : "=l"(d) : "f"(x), "f"(y));
}
__device__ __forceinline__ void unpack2(float& x, float& y, ull d) {
    asm("mov.b64 {%0,%1},%2;" : "=f"(x), "=f"(y) : "l"(d));
}

// ---------------- constexpr CG machinery (compile-time only) ----------------

__host__ __device__ constexpr double cfact(int n) {
    double r = 1.0;
    for (int i = 2; i <= n; ++i) r *= (double)i;
    return r;
}

__host__ __device__ constexpr double csqrt_(double x) {
    if (x <= 0.0) return 0.0;
    double g = (x >= 1.0) ? x : 1.0;
    for (int i = 0; i < 160; ++i) g = 0.5 * (g + x / g);
    return g;
}

__host__ __device__ constexpr double cg_coef(int j1, int m1, int j2, int m2, int j3, int m3) {
    if (m1 + m2 != m3) return 0.0;
    if (m1 < -j1 || m1 > j1 || m2 < -j2 || m2 > j2 || m3 < -j3 || m3 > j3) return 0.0;
    int lo = (j1 > j2) ? (j1 - j2) : (j2 - j1);
    if (j3 < lo || j3 > j1 + j2) return 0.0;
    double pref = csqrt_((2.0 * j3 + 1.0) * cfact(j3 + j1 - j2) * cfact(j3 - j1 + j2)
                         * cfact(j1 + j2 - j3) / cfact(j1 + j2 + j3 + 1));
    pref = pref * csqrt_(cfact(j3 + m3) * cfact(j3 - m3) * cfact(j1 - m1) * cfact(j1 + m1)
                         * cfact(j2 - m2) * cfact(j2 + m2));
    double s = 0.0;
    for (int k = 0; k <= j1 + j2 - j3; ++k) {
        int a2 = j1 + j2 - j3 - k;
        int a3 = j1 - m1 - k;
        int a4 = j2 + m2 - k;
        int a5 = j3 - j2 + m1 + k;
        int a6 = j3 - j1 - m2 + k;
        if (a2 < 0 || a3 < 0 || a4 < 0 || a5 < 0 || a6 < 0) continue;
        double den = cfact(k) * cfact(a2) * cfact(a3) * cfact(a4) * cfact(a5) * cfact(a6);
        s += ((k & 1) ? -1.0 : 1.0) / den;
    }
    return pref * s;
}

// output base (in floats, within one batch row) of tuple (L, L1, L2)
__host__ __device__ constexpr int out_base_f(int L1, int L2, int L) {
    int off = 0;
    for (int l = 0; l <= LMAXV; ++l)
        for (int l1 = 0; l1 <= LMAXV; ++l1)
            for (int l2 = 0; l2 <= LMAXV; ++l2) {
                int lo = (l1 > l2) ? (l1 - l2) : (l2 - l1);
                if (!(lo <= l && l <= l1 + l2)) continue;
                if (l == L && l1 == L1 && l2 == L2) return off;
                off += 1024 * (2 * l + 1) * 2;
            }
    return 0;
}

// float offset of region L within the all-L smem image
__host__ __device__ constexpr int pref_region(int L1, int L2, int L) {
    int lo = (L1 > L2) ? (L1 - L2) : (L2 - L1);
    int off = 0;
    for (int l = lo; l < L; ++l) off += 256 * (2 * l + 1);
    return off;
}

// ---------------- per-M computation ----------------

// accumulate one product (pr,pi) into all valid L for this (M, m1)
template <int L1, int L2, int M, int M1, int LS, int HI, int L>
__device__ __forceinline__ void acc_L(float pr, float pi, float* accr, float* acci) {
    if constexpr (L <= HI) {
        constexpr double cd = cg_coef(L1, M1, L2, M - M1, L, M);
        if constexpr (cd != 0.0) {
            constexpr float c = (float)cd;
            accr[L - LS] = fmaf(c, pr, accr[L - LS]);
            acci[L - LS] = fmaf(c, pi, acci[L - LS]);
        }
        acc_L<L1, L2, M, M1, LS, HI, L + 1>(pr, pi, accr, acci);
    }
}

// loop over m1 for fixed M: one packed product per (m1, m2=M-m1)
template <int L1, int L2, int M, int M1, int M1HI, int LS, int HI>
__device__ __forceinline__ void terms_m1(const ull* A2r, const ull* A2i,
                                         const ull* B2, const ull* BN2,
                                         float* accr, float* acci) {
    if constexpr (M1 <= M1HI) {
        ull t, p;
        mul2(t, A2i[M1 + L1], BN2[M - M1 + L2]);     // (ai*-bi, ai*br)
        fma2p(p, A2r[M1 + L1], B2[M - M1 + L2], t);  // (pr, pi)
        float pr, pi;
        unpack2(pr, pi, p);
        acc_L<L1, L2, M, M1, LS, HI, LS>(pr, pi, accr, acci);
        terms_m1<L1, L2, M, M1 + 1, M1HI, LS, HI>(A2r, A2i, B2, BN2, accr, acci);
    }
}

// scatter finished (L,M) accumulators into the all-L smem image
template <int L1, int L2, int M, int LS, int HI, int L>
__device__ __forceinline__ void st_acc(const float* accr, const float* acci,
                                       float* img, int warp, int lane) {
    if constexpr (L <= HI) {
        constexpr int TW = 2 * L + 1;
        constexpr int PR = pref_region(L1, L2, L);
        float2* dst = (float2*)(img + PR) + warp * (32 * TW) + lane * TW + (M + L);
        *dst = make_float2(accr[L - LS], acci[L - LS]);
        st_acc<L1, L2, M, LS, HI, L + 1>(accr, acci, img, warp, lane);
    }
}

template <int L1, int L2, int M>
__device__ __forceinline__ void do_M(const ull* A2r, const ull* A2i,
                                     const ull* B2, const ull* BN2,
                                     float* img, int warp, int lane) {
    constexpr int LO = (L1 > L2) ? (L1 - L2) : (L2 - L1);
    constexpr int HI = (L1 + L2 < LMAXV) ? (L1 + L2) : LMAXV;
    constexpr int AM = (M < 0) ? -M : M;
    constexpr int LS = (AM > LO) ? AM : LO;
    if constexpr (LS <= HI) {
        constexpr int NL = HI - LS + 1;
        float accr[NL], acci[NL];
#pragma unroll
        for (int i = 0; i < NL; ++i) { accr[i] = 0.f; acci[i] = 0.f; }
        constexpr int M1LO = ((-L1) > (M - L2)) ? (-L1) : (M - L2);
        constexpr int M1HI = (L1 < (M + L2)) ? L1 : (M + L2);
        terms_m1<L1, L2, M, M1LO, M1HI, LS, HI>(A2r, A2i, B2, BN2, accr, acci);
        st_acc<L1, L2, M, LS, HI, LS>(accr, acci, img, warp, lane);
    }
}

template <int L1, int L2, int M, int MHI>
__device__ __forceinline__ void all_M(const ull* A2r, const ull* A2i,
                                      const ull* B2, const ull* BN2,
                                      float* img, int warp, int lane) {
    if constexpr (M <= MHI) {
        do_M<L1, L2, M>(A2r, A2i, B2, BN2, img, warp, lane);
        all_M<L1, L2, M + 1, MHI>(A2r, A2i, B2, BN2, img, warp, lane);
    }
}

// issue one bulk TMA store per L region of the image
template <int L1, int L2, int L>
__device__ __forceinline__ void bulk_L(float* img, float* outb, int tbase) {
    constexpr int HI = (L1 + L2 < LMAXV) ? (L1 + L2) : LMAXV;
    if constexpr (L <= HI) {
        constexpr int TW = 2 * L + 1;
        constexpr int PR = pref_region(L1, L2, L);
        constexpr int OB = out_base_f(L1, L2, L);
        float* g = outb + OB + tbase * (64 * TW);
        unsigned sa = (unsigned)__cvta_generic_to_shared(img + PR);
        asm volatile("cp.async.bulk.global.shared::cta.bulk_group [%0],[%1],%2;"
                     :: "l"(g), "r"(sa), "r"(1024 * TW) : "memory");
        bulk_L<L1, L2, L + 1>(img, outb, tbase);
    }
}

// ---------------- per-pair block body (8 t1 groups = full pair x batch) -----

template <int L1, int L2>
__device__ __forceinline__ void block_work(const float* __restrict__ fs,
                                           float* __restrict__ out,
                                           float* s1, float* s2, float* simg,
                                           int b) {
    const int tid = threadIdx.x;
    const int warp = tid >> 5;
    const int lane = tid & 31;
    constexpr int LO = (L1 > L2) ? (L1 - L2) : (L2 - L1);
    constexpr int HI = (L1 + L2 < LMAXV) ? (L1 + L2) : LMAXV;
    constexpr int SUMTW = (HI + 1) * (HI + 1) - LO * LO;   // total 2l+1 span
    constexpr bool DB = (2 * 256 * SUMTW <= IMG_F);        // double-buffer fits?

    // stage input fragments (each is 32*(2l+1) float2, contiguous in gmem)
    {
        const float4* i1 = (const float4*)(fs + (size_t)b * 2304 + 64 * L1 * L1);
        const float4* i2 = (const float4*)(fs + (size_t)b * 2304 + 64 * L2 * L2);
        constexpr int N1 = 16 * (2 * L1 + 1);
        constexpr int N2 = 16 * (2 * L2 + 1);
#pragma unroll
        for (int j = tid; j < N1; j += 128) ((float4*)s1)[j] = i1[j];
#pragma unroll
        for (int j = tid; j < N2; j += 128) ((float4*)s2)[j] = i2[j];
    }
    __syncthreads();

    // B side (per lane = t2): natural packs (br,bi) + swapped-neg packs (-bi,br)
    ull B2[2 * L2 + 1], BN2[2 * L2 + 1];
    {
        const ull* bv = (const ull*)s2 + lane * (2 * L2 + 1);
#pragma unroll
        for (int i = 0; i < 2 * L2 + 1; ++i) {
            B2[i] = bv[i];
            float br, bi;
            unpack2(br, bi, B2[i]);
            pack2(BN2[i], -bi, br);
        }
    }

    float* outb = out + (size_t)b * ROWF;

#pragma unroll 1
    for (int iter = 0; iter < 8; ++iter) {
        const int t1 = iter * 4 + warp;
        float* img = DB ? (simg + (iter & 1) * (256 * SUMTW)) : simg;

        // A side: dup packs (ar,ar) and (ai,ai) per m1
        ull A2r[2 * L1 + 1], A2i[2 * L1 + 1];
        {
            const ull* av = (const ull*)s1 + t1 * (2 * L1 + 1);
#pragma unroll
            for (int i = 0; i < 2 * L1 + 1; ++i) {
                float ar, ai;
                ull a = av[i];
                unpack2(ar, ai, a);
                pack2(A2r[i], ar, ar);
                pack2(A2i[i], ai, ai);
            }
        }

        // acquire image buffer: with double-buffer, allow the previous group
        // to still be reading (wait only for the one before it)
        if (tid == 0) {
            if (DB)
                asm volatile("cp.async.bulk.wait_group.read 1;" ::: "memory");
            else
                asm volatile("cp.async.bulk.wait_group.read 0;" ::: "memory");
        }
        __syncthreads();

        all_M<L1, L2, -HI, HI>(A2r, A2i, B2, BN2, img, warp, lane);

        // make generic-proxy STS visible to the async (TMA) proxy
        asm volatile("fence.proxy.async.shared::cta;" ::: "memory");
        __syncthreads();

        if (tid == 0) {
            bulk_L<L1, L2, LO>(img, outb, iter * 4);
            asm volatile("cp.async.bulk.commit_group;" ::: "memory");
        }
    }

    // drain: all bulk stores must complete before the block exits (smem dies)
    if (tid == 0)
        asm volatile("cp.async.bulk.wait_group 0;" ::: "memory");
    __syncthreads();
}

// ---------------- kernel ----------------

// heavy-first (LPT) pair schedule: p = l1*6+l2, by (2l1+1)(2l2+1) descending
__device__ __constant__ int PAIR_ORDER[36] = {
    35, 29, 34, 28, 23, 33, 22, 27, 32, 17, 21, 26,
    16, 15, 20, 31, 11, 25, 10, 14, 19,  9,  8, 13,
    30,  5, 24,  4,  7, 18,  3,  2, 12,  1,  6,  0
};

__global__ void __launch_bounds__(128, 5)
cg_sparse_kernel(const float* __restrict__ fs, float* __restrict__ out) {
    __shared__ __align__(16) float s1[704];
    __shared__ __align__(16) float s2[704];
    __shared__ __align__(16) float simg[IMG_F];

    const int bx = blockIdx.x;
    const int b = bx & 31;
    const int p = PAIR_ORDER[bx >> 5];   // heavy pairs first (LPT)

#define PCASE(P, A_, B_) case P: block_work<A_, B_>(fs, out, s1, s2, simg, b); break;
    switch (p) {
        PCASE(0, 0, 0)  PCASE(1, 0, 1)  PCASE(2, 0, 2)  PCASE(3, 0, 3)  PCASE(4, 0, 4)  PCASE(5, 0, 5)
        PCASE(6, 1, 0)  PCASE(7, 1, 1)  PCASE(8, 1, 2)  PCASE(9, 1, 3)  PCASE(10, 1, 4) PCASE(11, 1, 5)
        PCASE(12, 2, 0) PCASE(13, 2, 1) PCASE(14, 2, 2) PCASE(15, 2, 3) PCASE(16, 2, 4) PCASE(17, 2, 5)
        PCASE(18, 3, 0) PCASE(19, 3, 1) PCASE(20, 3, 2) PCASE(21, 3, 3) PCASE(22, 3, 4) PCASE(23, 3, 5)
        PCASE(24, 4, 0) PCASE(25, 4, 1) PCASE(26, 4, 2) PCASE(27, 4, 3) PCASE(28, 4, 4) PCASE(29, 4, 5)
        PCASE(30, 5, 0) PCASE(31, 5, 1) PCASE(32, 5, 2) PCASE(33, 5, 3) PCASE(34, 5, 4) PCASE(35, 5, 5)
        default: break;
    }
#undef PCASE
}

extern "C" void kernel_launch(void* const* d_in, const int* in_sizes, int n_in,
                              void* d_out, int out_size) {
    const float* fs = (const float*)d_in[0];
    float* out = (float*)d_out;
    cg_sparse_kernel<<<NBLOCKS, 128>>>(fs, out);
}

// round 14
// speedup vs baseline: 1.2100x; 1.2100x over previous
#include <cuda_runtime.h>

typedef unsigned long long ull;

// ----------------------------------------------------------------------------
// Clebsch-Gordan sparse product, LMAX=5, TAU=32, BATCH=32.
// R14 = R11 (M-grouped packed-f32x2 products, imm-FFMA CG accumulation, all-L
// smem image + bulk TMA stores, 8 iters/block, grid 36*32 LPT) + COMPILE-TIME
// double-buffered image for pairs with SUMTW <= 18: the iter loop is unrolled
// by 2 so each phase's image base is a constant offset (no runtime base, no
// spills — R13's failure mode). DB phases use wait_group.read 1, hiding the
// TMA smem-read round trip behind the next iter's compute.
// ----------------------------------------------------------------------------

#define LMAXV 5
#define ROWF  1579008            // output floats per batch row
#define NBLOCKS (36*32)          // pairOrder(36, slowest) * b(32)
#define IMG_F 9216               // image region: 256 * sum(2l+1, l=0..5) floats

// ---------------- packed f32x2 helpers ----------------

__device__ __forceinline__ void mul2(ull& d, ull a, ull b) {
    asm("mul.rn.f32x2 %0,%1,%2;" : "=l"(d) : "l"(a), "l"(b));
}
__device__ __forceinline__ void fma2p(ull& d, ull a, ull b, ull c) {
    asm("fma.rn.f32x2 %0,%1,%2,%3;" : "=l"(d) : "l"(a), "l"(b), "l"(c));
}
__device__ __forceinline__ void pack2(ull& d, float x, float y) {
    asm("mov.b64 %0,{%1,%2};" : "=l"(d) : "f"(x), "f"(y));
}
__device__ __forceinline__ void unpack2(float& x, float& y, ull d) {
    asm("mov.b64 {%0,%1},%2;" : "=f"(x), "=f"(y) : "l"(d));
}

// ---------------- constexpr CG machinery (compile-time only) ----------------

__host__ __device__ constexpr double cfact(int n) {
    double r = 1.0;
    for (int i = 2; i <= n; ++i) r *= (double)i;
    return r;
}

__host__ __device__ constexpr double csqrt_(double x) {
    if (x <= 0.0) return 0.0;
    double g = (x >= 1.0) ? x : 1.0;
    for (int i = 0; i < 160; ++i) g = 0.5 * (g + x / g);
    return g;
}

__host__ __device__ constexpr double cg_coef(int j1, int m1, int j2, int m2, int j3, int m3) {
    if (m1 + m2 != m3) return 0.0;
    if (m1 < -j1 || m1 > j1 || m2 < -j2 || m2 > j2 || m3 < -j3 || m3 > j3) return 0.0;
    int lo = (j1 > j2) ? (j1 - j2) : (j2 - j1);
    if (j3 < lo || j3 > j1 + j2) return 0.0;
    double pref = csqrt_((2.0 * j3 + 1.0) * cfact(j3 + j1 - j2) * cfact(j3 - j1 + j2)
                         * cfact(j1 + j2 - j3) / cfact(j1 + j2 + j3 + 1));
    pref = pref * csqrt_(cfact(j3 + m3) * cfact(j3 - m3) * cfact(j1 - m1) * cfact(j1 + m1)
                         * cfact(j2 - m2) * cfact(j2 + m2));
    double s = 0.0;
    for (int k = 0; k <= j1 + j2 - j3; ++k) {
        int a2 = j1 + j2 - j3 - k;
        int a3 = j1 - m1 - k;
        int a4 = j2 + m2 - k;
        int a5 = j3 - j2 + m1 + k;
        int a6 = j3 - j1 - m2 + k;
        if (a2 < 0 || a3 < 0 || a4 < 0 || a5 < 0 || a6 < 0) continue;
        double den = cfact(k) * cfact(a2) * cfact(a3) * cfact(a4) * cfact(a5) * cfact(a6);
        s += ((k & 1) ? -1.0 : 1.0) / den;
    }
    return pref * s;
}

// output base (in floats, within one batch row) of tuple (L, L1, L2)
__host__ __device__ constexpr int out_base_f(int L1, int L2, int L) {
    int off = 0;
    for (int l = 0; l <= LMAXV; ++l)
        for (int l1 = 0; l1 <= LMAXV; ++l1)
            for (int l2 = 0; l2 <= LMAXV; ++l2) {
                int lo = (l1 > l2) ? (l1 - l2) : (l2 - l1);
                if (!(lo <= l && l <= l1 + l2)) continue;
                if (l == L && l1 == L1 && l2 == L2) return off;
                off += 1024 * (2 * l + 1) * 2;
            }
    return 0;
}

// float offset of region L within the all-L smem image
__host__ __device__ constexpr int pref_region(int L1, int L2, int L) {
    int lo = (L1 > L2) ? (L1 - L2) : (L2 - L1);
    int off = 0;
    for (int l = lo; l < L; ++l) off += 256 * (2 * l + 1);
    return off;
}

// ---------------- per-M computation ----------------

// accumulate one product (pr,pi) into all valid L for this (M, m1)
template <int L1, int L2, int M, int M1, int LS, int HI, int L>
__device__ __forceinline__ void acc_L(float pr, float pi, float* accr, float* acci) {
    if constexpr (L <= HI) {
        constexpr double cd = cg_coef(L1, M1, L2, M - M1, L, M);
        if constexpr (cd != 0.0) {
            constexpr float c = (float)cd;
            accr[L - LS] = fmaf(c, pr, accr[L - LS]);
            acci[L - LS] = fmaf(c, pi, acci[L - LS]);
        }
        acc_L<L1, L2, M, M1, LS, HI, L + 1>(pr, pi, accr, acci);
    }
}

// loop over m1 for fixed M: one packed product per (m1, m2=M-m1)
template <int L1, int L2, int M, int M1, int M1HI, int LS, int HI>
__device__ __forceinline__ void terms_m1(const ull* A2r, const ull* A2i,
                                         const ull* B2, const ull* BN2,
                                         float* accr, float* acci) {
    if constexpr (M1 <= M1HI) {
        ull t, p;
        mul2(t, A2i[M1 + L1], BN2[M - M1 + L2]);     // (ai*-bi, ai*br)
        fma2p(p, A2r[M1 + L1], B2[M - M1 + L2], t);  // (pr, pi)
        float pr, pi;
        unpack2(pr, pi, p);
        acc_L<L1, L2, M, M1, LS, HI, LS>(pr, pi, accr, acci);
        terms_m1<L1, L2, M, M1 + 1, M1HI, LS, HI>(A2r, A2i, B2, BN2, accr, acci);
    }
}

// scatter finished (L,M) accumulators into the all-L smem image
template <int L1, int L2, int M, int LS, int HI, int L>
__device__ __forceinline__ void st_acc(const float* accr, const float* acci,
                                       float* img, int warp, int lane) {
    if constexpr (L <= HI) {
        constexpr int TW = 2 * L + 1;
        constexpr int PR = pref_region(L1, L2, L);
        float2* dst = (float2*)(img + PR) + warp * (32 * TW) + lane * TW + (M + L);
        *dst = make_float2(accr[L - LS], acci[L - LS]);
        st_acc<L1, L2, M, LS, HI, L + 1>(accr, acci, img, warp, lane);
    }
}

template <int L1, int L2, int M>
__device__ __forceinline__ void do_M(const ull* A2r, const ull* A2i,
                                     const ull* B2, const ull* BN2,
                                     float* img, int warp, int lane) {
    constexpr int LO = (L1 > L2) ? (L1 - L2) : (L2 - L1);
    constexpr int HI = (L1 + L2 < LMAXV) ? (L1 + L2) : LMAXV;
    constexpr int AM = (M < 0) ? -M : M;
    constexpr int LS = (AM > LO) ? AM : LO;
    if constexpr (LS <= HI) {
        constexpr int NL = HI - LS + 1;
        float accr[NL], acci[NL];
#pragma unroll
        for (int i = 0; i < NL; ++i) { accr[i] = 0.f; acci[i] = 0.f; }
        constexpr int M1LO = ((-L1) > (M - L2)) ? (-L1) : (M - L2);
        constexpr int M1HI = (L1 < (M + L2)) ? L1 : (M + L2);
        terms_m1<L1, L2, M, M1LO, M1HI, LS, HI>(A2r, A2i, B2, BN2, accr, acci);
        st_acc<L1, L2, M, LS, HI, LS>(accr, acci, img, warp, lane);
    }
}

template <int L1, int L2, int M, int MHI>
__device__ __forceinline__ void all_M(const ull* A2r, const ull* A2i,
                                      const ull* B2, const ull* BN2,
                                      float* img, int warp, int lane) {
    if constexpr (M <= MHI) {
        do_M<L1, L2, M>(A2r, A2i, B2, BN2, img, warp, lane);
        all_M<L1, L2, M + 1, MHI>(A2r, A2i, B2, BN2, img, warp, lane);
    }
}

// issue one bulk TMA store per L region of the image
template <int L1, int L2, int L>
__device__ __forceinline__ void bulk_L(float* img, float* outb, int tbase) {
    constexpr int HI = (L1 + L2 < LMAXV) ? (L1 + L2) : LMAXV;
    if constexpr (L <= HI) {
        constexpr int TW = 2 * L + 1;
        constexpr int PR = pref_region(L1, L2, L);
        constexpr int OB = out_base_f(L1, L2, L);
        float* g = outb + OB + tbase * (64 * TW);
        unsigned sa = (unsigned)__cvta_generic_to_shared(img + PR);
        asm volatile("cp.async.bulk.global.shared::cta.bulk_group [%0],[%1],%2;"
                     :: "l"(g), "r"(sa), "r"(1024 * TW) : "memory");
        bulk_L<L1, L2, L + 1>(img, outb, tbase);
    }
}

// ---------------- one iteration (4 t1 tiles -> image -> bulk stores) --------

template <int L1, int L2, bool DB>
__device__ __forceinline__ void iter_body(const float* s1,
                                          const ull* B2, const ull* BN2,
                                          float* img, float* outb, int iter,
                                          int warp, int lane, int tid) {
    constexpr int LO = (L1 > L2) ? (L1 - L2) : (L2 - L1);
    constexpr int HI = (L1 + L2 < LMAXV) ? (L1 + L2) : LMAXV;

    const int t1 = iter * 4 + warp;

    // A side: dup packs (ar,ar) and (ai,ai) per m1
    ull A2r[2 * L1 + 1], A2i[2 * L1 + 1];
    {
        const ull* av = (const ull*)s1 + t1 * (2 * L1 + 1);
#pragma unroll
        for (int i = 0; i < 2 * L1 + 1; ++i) {
            float ar, ai;
            ull a = av[i];
            unpack2(ar, ai, a);
            pack2(A2r[i], ar, ar);
            pack2(A2i[i], ai, ai);
        }
    }

    // acquire image buffer: DB allows the previous group to still be reading
    if (tid == 0) {
        if (DB)
            asm volatile("cp.async.bulk.wait_group.read 1;" ::: "memory");
        else
            asm volatile("cp.async.bulk.wait_group.read 0;" ::: "memory");
    }
    __syncthreads();

    all_M<L1, L2, -HI, HI>(A2r, A2i, B2, BN2, img, warp, lane);

    // make generic-proxy STS visible to the async (TMA) proxy
    asm volatile("fence.proxy.async.shared::cta;" ::: "memory");
    __syncthreads();

    if (tid == 0) {
        bulk_L<L1, L2, LO>(img, outb, iter * 4);
        asm volatile("cp.async.bulk.commit_group;" ::: "memory");
    }
}

// ---------------- per-pair block body (8 t1 groups = full pair x batch) -----

template <int L1, int L2>
__device__ __forceinline__ void block_work(const float* __restrict__ fs,
                                           float* __restrict__ out,
                                           float* s1, float* s2, float* simg,
                                           int b) {
    const int tid = threadIdx.x;
    const int warp = tid >> 5;
    const int lane = tid & 31;
    constexpr int LO = (L1 > L2) ? (L1 - L2) : (L2 - L1);
    constexpr int HI = (L1 + L2 < LMAXV) ? (L1 + L2) : LMAXV;
    constexpr int SUMTW = (HI + 1) * (HI + 1) - LO * LO;   // total 2l+1 span
    constexpr bool DB = (2 * 256 * SUMTW <= IMG_F);        // double-buffer fits?

    // stage input fragments (each is 32*(2l+1) float2, contiguous in gmem)
    {
        const float4* i1 = (const float4*)(fs + (size_t)b * 2304 + 64 * L1 * L1);
        const float4* i2 = (const float4*)(fs + (size_t)b * 2304 + 64 * L2 * L2);
        constexpr int N1 = 16 * (2 * L1 + 1);
        constexpr int N2 = 16 * (2 * L2 + 1);
#pragma unroll
        for (int j = tid; j < N1; j += 128) ((float4*)s1)[j] = i1[j];
#pragma unroll
        for (int j = tid; j < N2; j += 128) ((float4*)s2)[j] = i2[j];
    }
    __syncthreads();

    // B side (per lane = t2): natural packs (br,bi) + swapped-neg packs (-bi,br)
    ull B2[2 * L2 + 1], BN2[2 * L2 + 1];
    {
        const ull* bv = (const ull*)s2 + lane * (2 * L2 + 1);
#pragma unroll
        for (int i = 0; i < 2 * L2 + 1; ++i) {
            B2[i] = bv[i];
            float br, bi;
            unpack2(br, bi, B2[i]);
            pack2(BN2[i], -bi, br);
        }
    }

    float* outb = out + (size_t)b * ROWF;

    if constexpr (DB) {
        // unrolled by 2: both buffer bases are COMPILE-TIME offsets off simg
#pragma unroll 1
        for (int it2 = 0; it2 < 4; ++it2) {
            iter_body<L1, L2, true>(s1, B2, BN2, simg,
                                    outb, 2 * it2 + 0, warp, lane, tid);
            iter_body<L1, L2, true>(s1, B2, BN2, simg + 256 * SUMTW,
                                    outb, 2 * it2 + 1, warp, lane, tid);
        }
    } else {
#pragma unroll 1
        for (int iter = 0; iter < 8; ++iter) {
            iter_body<L1, L2, false>(s1, B2, BN2, simg,
                                     outb, iter, warp, lane, tid);
        }
    }

    // drain: all bulk stores must complete before the block exits (smem dies)
    if (tid == 0)
        asm volatile("cp.async.bulk.wait_group 0;" ::: "memory");
    __syncthreads();
}

// ---------------- kernel ----------------

// heavy-first (LPT) pair schedule: p = l1*6+l2, by (2l1+1)(2l2+1) descending
__device__ __constant__ int PAIR_ORDER[36] = {
    35, 29, 34, 28, 23, 33, 22, 27, 32, 17, 21, 26,
    16, 15, 20, 31, 11, 25, 10, 14, 19,  9,  8, 13,
    30,  5, 24,  4,  7, 18,  3,  2, 12,  1,  6,  0
};

__global__ void __launch_bounds__(128, 5)
cg_sparse_kernel(const float* __restrict__ fs, float* __restrict__ out) {
    __shared__ __align__(16) float s1[704];
    __shared__ __align__(16) float s2[704];
    __shared__ __align__(16) float simg[IMG_F];

    const int bx = blockIdx.x;
    const int b = bx & 31;
    const int p = PAIR_ORDER[bx >> 5];   // heavy pairs first (LPT)

#define PCASE(P, A_, B_) case P: block_work<A_, B_>(fs, out, s1, s2, simg, b); break;
    switch (p) {
        PCASE(0, 0, 0)  PCASE(1, 0, 1)  PCASE(2, 0, 2)  PCASE(3, 0, 3)  PCASE(4, 0, 4)  PCASE(5, 0, 5)
        PCASE(6, 1, 0)  PCASE(7, 1, 1)  PCASE(8, 1, 2)  PCASE(9, 1, 3)  PCASE(10, 1, 4) PCASE(11, 1, 5)
        PCASE(12, 2, 0) PCASE(13, 2, 1) PCASE(14, 2, 2) PCASE(15, 2, 3) PCASE(16, 2, 4) PCASE(17, 2, 5)
        PCASE(18, 3, 0) PCASE(19, 3, 1) PCASE(20, 3, 2) PCASE(21, 3, 3) PCASE(22, 3, 4) PCASE(23, 3, 5)
        PCASE(24, 4, 0) PCASE(25, 4, 1) PCASE(26, 4, 2) PCASE(27, 4, 3) PCASE(28, 4, 4) PCASE(29, 4, 5)
        PCASE(30, 5, 0) PCASE(31, 5, 1) PCASE(32, 5, 2) PCASE(33, 5, 3) PCASE(34, 5, 4) PCASE(35, 5, 5)
        default: break;
    }
#undef PCASE
}

extern "C" void kernel_launch(void* const* d_in, const int* in_sizes, int n_in,
                              void* d_out, int out_size) {
    const float* fs = (const float*)d_in[0];
    float* out = (float*)d_out;
    cg_sparse_kernel<<<NBLOCKS, 128>>>(fs, out);
}

// round 15
// speedup vs baseline: 1.2678x; 1.0478x over previous
#include <cuda_runtime.h>

typedef unsigned long long ull;

// ----------------------------------------------------------------------------
// Clebsch-Gordan sparse product, LMAX=5, TAU=32, BATCH=32.
// R15 = R11 (M-grouped packed-f32x2 products, imm-FFMA CG accumulation, all-L
// smem image + bulk TMA stores, grid 36*32 LPT) + MULTI-TILE ROUNDS for light
// pairs: each warp processes NT tiles per round (NT in {1,2,4,8}, largest with
// NT*256*SUMTW <= IMG_F), cutting the serialized round count 8 -> 8/NT.
// The NT loop is a runtime unroll-1 loop with block-uniform tile index: no
// per-pair code duplication (R13/R14's failure mode). Heavy pairs have NT=1
// and compile to R11's codegen.
// ----------------------------------------------------------------------------

#define LMAXV 5
#define ROWF  1579008            // output floats per batch row
#define NBLOCKS (36*32)          // pairOrder(36, slowest) * b(32)
#define IMG_F 9216               // image region: 256 * sum(2l+1, l=0..5) floats

// ---------------- packed f32x2 helpers ----------------

__device__ __forceinline__ void mul2(ull& d, ull a, ull b) {
    asm("mul.rn.f32x2 %0,%1,%2;" : "=l"(d) : "l"(a), "l"(b));
}
__device__ __forceinline__ void fma2p(ull& d, ull a, ull b, ull c) {
    asm("fma.rn.f32x2 %0,%1,%2,%3;" : "=l"(d) : "l"(a), "l"(b), "l"(c));
}
__device__ __forceinline__ void pack2(ull& d, float x, float y) {
    asm("mov.b64 %0,{%1,%2};" : "=l"(d) : "f"(x), "f"(y));
}
__device__ __forceinline__ void unpack2(float& x, float& y, ull d) {
    asm("mov.b64 {%0,%1},%2;" : "=f"(x), "=f"(y) : "l"(d));
}

// ---------------- constexpr CG machinery (compile-time only) ----------------

__host__ __device__ constexpr double cfact(int n) {
    double r = 1.0;
    for (int i = 2; i <= n; ++i) r *= (double)i;
    return r;
}

__host__ __device__ constexpr double csqrt_(double x) {
    if (x <= 0.0) return 0.0;
    double g = (x >= 1.0) ? x : 1.0;
    for (int i = 0; i < 160; ++i) g = 0.5 * (g + x / g);
    return g;
}

__host__ __device__ constexpr double cg_coef(int j1, int m1, int j2, int m2, int j3, int m3) {
    if (m1 + m2 != m3) return 0.0;
    if (m1 < -j1 || m1 > j1 || m2 < -j2 || m2 > j2 || m3 < -j3 || m3 > j3) return 0.0;
    int lo = (j1 > j2) ? (j1 - j2) : (j2 - j1);
    if (j3 < lo || j3 > j1 + j2) return 0.0;
    double pref = csqrt_((2.0 * j3 + 1.0) * cfact(j3 + j1 - j2) * cfact(j3 - j1 + j2)
                         * cfact(j1 + j2 - j3) / cfact(j1 + j2 + j3 + 1));
    pref = pref * csqrt_(cfact(j3 + m3) * cfact(j3 - m3) * cfact(j1 - m1) * cfact(j1 + m1)
                         * cfact(j2 - m2) * cfact(j2 + m2));
    double s = 0.0;
    for (int k = 0; k <= j1 + j2 - j3; ++k) {
        int a2 = j1 + j2 - j3 - k;
        int a3 = j1 - m1 - k;
        int a4 = j2 + m2 - k;
        int a5 = j3 - j2 + m1 + k;
        int a6 = j3 - j1 - m2 + k;
        if (a2 < 0 || a3 < 0 || a4 < 0 || a5 < 0 || a6 < 0) continue;
        double den = cfact(k) * cfact(a2) * cfact(a3) * cfact(a4) * cfact(a5) * cfact(a6);
        s += ((k & 1) ? -1.0 : 1.0) / den;
    }
    return pref * s;
}

// output base (in floats, within one batch row) of tuple (L, L1, L2)
__host__ __device__ constexpr int out_base_f(int L1, int L2, int L) {
    int off = 0;
    for (int l = 0; l <= LMAXV; ++l)
        for (int l1 = 0; l1 <= LMAXV; ++l1)
            for (int l2 = 0; l2 <= LMAXV; ++l2) {
                int lo = (l1 > l2) ? (l1 - l2) : (l2 - l1);
                if (!(lo <= l && l <= l1 + l2)) continue;
                if (l == L && l1 == L1 && l2 == L2) return off;
                off += 1024 * (2 * l + 1) * 2;
            }
    return 0;
}

// float offset of region L within the (unscaled) all-L smem image
__host__ __device__ constexpr int pref_region(int L1, int L2, int L) {
    int lo = (L1 > L2) ? (L1 - L2) : (L2 - L1);
    int off = 0;
    for (int l = lo; l < L; ++l) off += 256 * (2 * l + 1);
    return off;
}

// ---------------- per-M computation ----------------

// accumulate one product (pr,pi) into all valid L for this (M, m1)
template <int L1, int L2, int M, int M1, int LS, int HI, int L>
__device__ __forceinline__ void acc_L(float pr, float pi, float* accr, float* acci) {
    if constexpr (L <= HI) {
        constexpr double cd = cg_coef(L1, M1, L2, M - M1, L, M);
        if constexpr (cd != 0.0) {
            constexpr float c = (float)cd;
            accr[L - LS] = fmaf(c, pr, accr[L - LS]);
            acci[L - LS] = fmaf(c, pi, acci[L - LS]);
        }
        acc_L<L1, L2, M, M1, LS, HI, L + 1>(pr, pi, accr, acci);
    }
}

// loop over m1 for fixed M: one packed product per (m1, m2=M-m1)
template <int L1, int L2, int M, int M1, int M1HI, int LS, int HI>
__device__ __forceinline__ void terms_m1(const ull* A2r, const ull* A2i,
                                         const ull* B2, const ull* BN2,
                                         float* accr, float* acci) {
    if constexpr (M1 <= M1HI) {
        ull t, p;
        mul2(t, A2i[M1 + L1], BN2[M - M1 + L2]);     // (ai*-bi, ai*br)
        fma2p(p, A2r[M1 + L1], B2[M - M1 + L2], t);  // (pr, pi)
        float pr, pi;
        unpack2(pr, pi, p);
        acc_L<L1, L2, M, M1, LS, HI, LS>(pr, pi, accr, acci);
        terms_m1<L1, L2, M, M1 + 1, M1HI, LS, HI>(A2r, A2i, B2, BN2, accr, acci);
    }
}

// scatter finished (L,M) accumulators into the NT-scaled all-L smem image
template <int L1, int L2, int NT, int M, int LS, int HI, int L>
__device__ __forceinline__ void st_acc(const float* accr, const float* acci,
                                       float* img, int wtile, int lane) {
    if constexpr (L <= HI) {
        constexpr int TW = 2 * L + 1;
        constexpr int PR = NT * pref_region(L1, L2, L);
        float2* dst = (float2*)(img + PR) + wtile * (32 * TW) + lane * TW + (M + L);
        *dst = make_float2(accr[L - LS], acci[L - LS]);
        st_acc<L1, L2, NT, M, LS, HI, L + 1>(accr, acci, img, wtile, lane);
    }
}

template <int L1, int L2, int NT, int M>
__device__ __forceinline__ void do_M(const ull* A2r, const ull* A2i,
                                     const ull* B2, const ull* BN2,
                                     float* img, int wtile, int lane) {
    constexpr int LO = (L1 > L2) ? (L1 - L2) : (L2 - L1);
    constexpr int HI = (L1 + L2 < LMAXV) ? (L1 + L2) : LMAXV;
    constexpr int AM = (M < 0) ? -M : M;
    constexpr int LS = (AM > LO) ? AM : LO;
    if constexpr (LS <= HI) {
        constexpr int NL = HI - LS + 1;
        float accr[NL], acci[NL];
#pragma unroll
        for (int i = 0; i < NL; ++i) { accr[i] = 0.f; acci[i] = 0.f; }
        constexpr int M1LO = ((-L1) > (M - L2)) ? (-L1) : (M - L2);
        constexpr int M1HI = (L1 < (M + L2)) ? L1 : (M + L2);
        terms_m1<L1, L2, M, M1LO, M1HI, LS, HI>(A2r, A2i, B2, BN2, accr, acci);
        st_acc<L1, L2, NT, M, LS, HI, LS>(accr, acci, img, wtile, lane);
    }
}

template <int L1, int L2, int NT, int M, int MHI>
__device__ __forceinline__ void all_M(const ull* A2r, const ull* A2i,
                                      const ull* B2, const ull* BN2,
                                      float* img, int wtile, int lane) {
    if constexpr (M <= MHI) {
        do_M<L1, L2, NT, M>(A2r, A2i, B2, BN2, img, wtile, lane);
        all_M<L1, L2, NT, M + 1, MHI>(A2r, A2i, B2, BN2, img, wtile, lane);
    }
}

// issue one bulk TMA store per L region of the NT-scaled image
template <int L1, int L2, int NT, int L>
__device__ __forceinline__ void bulk_L(float* img, float* outb, int tbase) {
    constexpr int HI = (L1 + L2 < LMAXV) ? (L1 + L2) : LMAXV;
    if constexpr (L <= HI) {
        constexpr int TW = 2 * L + 1;
        constexpr int PR = NT * pref_region(L1, L2, L);
        constexpr int OB = out_base_f(L1, L2, L);
        float* g = outb + OB + tbase * (64 * TW);
        unsigned sa = (unsigned)__cvta_generic_to_shared(img + PR);
        asm volatile("cp.async.bulk.global.shared::cta.bulk_group [%0],[%1],%2;"
                     :: "l"(g), "r"(sa), "r"(NT * 1024 * TW) : "memory");
        bulk_L<L1, L2, NT, L + 1>(img, outb, tbase);
    }
}

// ---------------- per-pair block body (8/NT rounds x NT tiles/warp) ---------

template <int L1, int L2>
__device__ __forceinline__ void block_work(const float* __restrict__ fs,
                                           float* __restrict__ out,
                                           float* s1, float* s2, float* simg,
                                           int b) {
    const int tid = threadIdx.x;
    const int warp = tid >> 5;
    const int lane = tid & 31;
    constexpr int LO = (L1 > L2) ? (L1 - L2) : (L2 - L1);
    constexpr int HI = (L1 + L2 < LMAXV) ? (L1 + L2) : LMAXV;
    constexpr int SUMTW = (HI + 1) * (HI + 1) - LO * LO;   // total 2l+1 span
    constexpr int NT = (256 * 8 * SUMTW <= IMG_F) ? 8
                     : (256 * 4 * SUMTW <= IMG_F) ? 4
                     : (256 * 2 * SUMTW <= IMG_F) ? 2 : 1;
    constexpr int ROUNDS = 8 / NT;

    // stage input fragments (each is 32*(2l+1) float2, contiguous in gmem)
    {
        const float4* i1 = (const float4*)(fs + (size_t)b * 2304 + 64 * L1 * L1);
        const float4* i2 = (const float4*)(fs + (size_t)b * 2304 + 64 * L2 * L2);
        constexpr int N1 = 16 * (2 * L1 + 1);
        constexpr int N2 = 16 * (2 * L2 + 1);
#pragma unroll
        for (int j = tid; j < N1; j += 128) ((float4*)s1)[j] = i1[j];
#pragma unroll
        for (int j = tid; j < N2; j += 128) ((float4*)s2)[j] = i2[j];
    }
    __syncthreads();

    // B side (per lane = t2): natural packs (br,bi) + swapped-neg packs (-bi,br)
    ull B2[2 * L2 + 1], BN2[2 * L2 + 1];
    {
        const ull* bv = (const ull*)s2 + lane * (2 * L2 + 1);
#pragma unroll
        for (int i = 0; i < 2 * L2 + 1; ++i) {
            B2[i] = bv[i];
            float br, bi;
            unpack2(br, bi, B2[i]);
            pack2(BN2[i], -bi, br);
        }
    }

    float* outb = out + (size_t)b * ROWF;

#pragma unroll 1
    for (int r = 0; r < ROUNDS; ++r) {
        // acquire image: previous round's TMA smem READS must be done (cheap —
        // does not wait for DRAM completion)
        if (tid == 0)
            asm volatile("cp.async.bulk.wait_group.read 0;" ::: "memory");
        __syncthreads();

#pragma unroll 1
        for (int j = 0; j < NT; ++j) {
            const int wtile = j * 4 + warp;
            const int t1 = r * (4 * NT) + wtile;

            // A side: dup packs (ar,ar) and (ai,ai) per m1
            ull A2r[2 * L1 + 1], A2i[2 * L1 + 1];
            {
                const ull* av = (const ull*)s1 + t1 * (2 * L1 + 1);
#pragma unroll
                for (int i = 0; i < 2 * L1 + 1; ++i) {
                    float ar, ai;
                    ull a = av[i];
                    unpack2(ar, ai, a);
                    pack2(A2r[i], ar, ar);
                    pack2(A2i[i], ai, ai);
                }
            }

            all_M<L1, L2, NT, -HI, HI>(A2r, A2i, B2, BN2, simg, wtile, lane);
        }

        // make generic-proxy STS visible to the async (TMA) proxy
        asm volatile("fence.proxy.async.shared::cta;" ::: "memory");
        __syncthreads();

        if (tid == 0) {
            bulk_L<L1, L2, NT, LO>(simg, outb, r * (4 * NT));
            asm volatile("cp.async.bulk.commit_group;" ::: "memory");
        }
    }

    // drain: all bulk stores must complete before the block exits (smem dies)
    if (tid == 0)
        asm volatile("cp.async.bulk.wait_group 0;" ::: "memory");
    __syncthreads();
}

// ---------------- kernel ----------------

// heavy-first (LPT) pair schedule: p = l1*6+l2, by (2l1+1)(2l2+1) descending
__device__ __constant__ int PAIR_ORDER[36] = {
    35, 29, 34, 28, 23, 33, 22, 27, 32, 17, 21, 26,
    16, 15, 20, 31, 11, 25, 10, 14, 19,  9,  8, 13,
    30,  5, 24,  4,  7, 18,  3,  2, 12,  1,  6,  0
};

__global__ void __launch_bounds__(128, 5)
cg_sparse_kernel(const float* __restrict__ fs, float* __restrict__ out) {
    __shared__ __align__(16) float s1[704];
    __shared__ __align__(16) float s2[704];
    __shared__ __align__(16) float simg[IMG_F];

    const int bx = blockIdx.x;
    const int b = bx & 31;
    const int p = PAIR_ORDER[bx >> 5];   // heavy pairs first (LPT)

#define PCASE(P, A_, B_) case P: block_work<A_, B_>(fs, out, s1, s2, simg, b); break;
    switch (p) {
        PCASE(0, 0, 0)  PCASE(1, 0, 1)  PCASE(2, 0, 2)  PCASE(3, 0, 3)  PCASE(4, 0, 4)  PCASE(5, 0, 5)
        PCASE(6, 1, 0)  PCASE(7, 1, 1)  PCASE(8, 1, 2)  PCASE(9, 1, 3)  PCASE(10, 1, 4) PCASE(11, 1, 5)
        PCASE(12, 2, 0) PCASE(13, 2, 1) PCASE(14, 2, 2) PCASE(15, 2, 3) PCASE(16, 2, 4) PCASE(17, 2, 5)
        PCASE(18, 3, 0) PCASE(19, 3, 1) PCASE(20, 3, 2) PCASE(21, 3, 3) PCASE(22, 3, 4) PCASE(23, 3, 5)
        PCASE(24, 4, 0) PCASE(25, 4, 1) PCASE(26, 4, 2) PCASE(27, 4, 3) PCASE(28, 4, 4) PCASE(29, 4, 5)
        PCASE(30, 5, 0) PCASE(31, 5, 1) PCASE(32, 5, 2) PCASE(33, 5, 3) PCASE(34, 5, 4) PCASE(35, 5, 5)
        default: break;
    }
#undef PCASE
}

extern "C" void kernel_launch(void* const* d_in, const int* in_sizes, int n_in,
                              void* d_out, int out_size) {
    const float* fs = (const float*)d_in[0];
    float* out = (float*)d_out;
    cg_sparse_kernel<<<NBLOCKS, 128>>>(fs, out);
}

// round 16
// speedup vs baseline: 1.3440x; 1.0601x over previous
#include <cuda_runtime.h>

typedef unsigned long long ull;

// ----------------------------------------------------------------------------
// Clebsch-Gordan sparse product, LMAX=5, TAU=32, BATCH=32.
// R16 = R11 (M-grouped packed-f32x2 products, imm-FFMA CG accumulation, all-L
// smem image + bulk TMA stores, LPT order) + HEAVY-PAIR SPLIT: the 6 heaviest
// pairs' blocks are split into two 4-iter halves running on different SMs
// (halves the heavy-block critical path); light pairs keep the proven 8-iter
// blocks. Grid 6*32*2 + 30*32 = 1344.
// ----------------------------------------------------------------------------

#define LMAXV 5
#define ROWF  1579008            // output floats per batch row
#define NBLOCKS 1344             // 384 heavy half-blocks + 960 light blocks
#define IMG_F 9216               // image region: 256 * sum(2l+1, l=0..5) floats

// ---------------- packed f32x2 helpers ----------------

__device__ __forceinline__ void mul2(ull& d, ull a, ull b) {
    asm("mul.rn.f32x2 %0,%1,%2;" : "=l"(d) : "l"(a), "l"(b));
}
__device__ __forceinline__ void fma2p(ull& d, ull a, ull b, ull c) {
    asm("fma.rn.f32x2 %0,%1,%2,%3;" : "=l"(d) : "l"(a), "l"(b), "l"(c));
}
__device__ __forceinline__ void pack2(ull& d, float x, float y) {
    asm("mov.b64 %0,{%1,%2};" : "=l"(d) : "f"(x), "f"(y));
}
__device__ __forceinline__ void unpack2(float& x, float& y, ull d) {
    asm("mov.b64 {%0,%1},%2;" : "=f"(x), "=f"(y) : "l"(d));
}

// ---------------- constexpr CG machinery (compile-time only) ----------------

__host__ __device__ constexpr double cfact(int n) {
    double r = 1.0;
    for (int i = 2; i <= n; ++i) r *= (double)i;
    return r;
}

__host__ __device__ constexpr double csqrt_(double x) {
    if (x <= 0.0) return 0.0;
    double g = (x >= 1.0) ? x : 1.0;
    for (int i = 0; i < 160; ++i) g = 0.5 * (g + x / g);
    return g;
}

__host__ __device__ constexpr double cg_coef(int j1, int m1, int j2, int m2, int j3, int m3) {
    if (m1 + m2 != m3) return 0.0;
    if (m1 < -j1 || m1 > j1 || m2 < -j2 || m2 > j2 || m3 < -j3 || m3 > j3) return 0.0;
    int lo = (j1 > j2) ? (j1 - j2) : (j2 - j1);
    if (j3 < lo || j3 > j1 + j2) return 0.0;
    double pref = csqrt_((2.0 * j3 + 1.0) * cfact(j3 + j1 - j2) * cfact(j3 - j1 + j2)
                         * cfact(j1 + j2 - j3) / cfact(j1 + j2 + j3 + 1));
    pref = pref * csqrt_(cfact(j3 + m3) * cfact(j3 - m3) * cfact(j1 - m1) * cfact(j1 + m1)
                         * cfact(j2 - m2) * cfact(j2 + m2));
    double s = 0.0;
    for (int k = 0; k <= j1 + j2 - j3; ++k) {
        int a2 = j1 + j2 - j3 - k;
        int a3 = j1 - m1 - k;
        int a4 = j2 + m2 - k;
        int a5 = j3 - j2 + m1 + k;
        int a6 = j3 - j1 - m2 + k;
        if (a2 < 0 || a3 < 0 || a4 < 0 || a5 < 0 || a6 < 0) continue;
        double den = cfact(k) * cfact(a2) * cfact(a3) * cfact(a4) * cfact(a5) * cfact(a6);
        s += ((k & 1) ? -1.0 : 1.0) / den;
    }
    return pref * s;
}

// output base (in floats, within one batch row) of tuple (L, L1, L2)
__host__ __device__ constexpr int out_base_f(int L1, int L2, int L) {
    int off = 0;
    for (int l = 0; l <= LMAXV; ++l)
        for (int l1 = 0; l1 <= LMAXV; ++l1)
            for (int l2 = 0; l2 <= LMAXV; ++l2) {
                int lo = (l1 > l2) ? (l1 - l2) : (l2 - l1);
                if (!(lo <= l && l <= l1 + l2)) continue;
                if (l == L && l1 == L1 && l2 == L2) return off;
                off += 1024 * (2 * l + 1) * 2;
            }
    return 0;
}

// float offset of region L within the all-L smem image
__host__ __device__ constexpr int pref_region(int L1, int L2, int L) {
    int lo = (L1 > L2) ? (L1 - L2) : (L2 - L1);
    int off = 0;
    for (int l = lo; l < L; ++l) off += 256 * (2 * l + 1);
    return off;
}

// ---------------- per-M computation ----------------

// accumulate one product (pr,pi) into all valid L for this (M, m1)
template <int L1, int L2, int M, int M1, int LS, int HI, int L>
__device__ __forceinline__ void acc_L(float pr, float pi, float* accr, float* acci) {
    if constexpr (L <= HI) {
        constexpr double cd = cg_coef(L1, M1, L2, M - M1, L, M);
        if constexpr (cd != 0.0) {
            constexpr float c = (float)cd;
            accr[L - LS] = fmaf(c, pr, accr[L - LS]);
            acci[L - LS] = fmaf(c, pi, acci[L - LS]);
        }
        acc_L<L1, L2, M, M1, LS, HI, L + 1>(pr, pi, accr, acci);
    }
}

// loop over m1 for fixed M: one packed product per (m1, m2=M-m1)
template <int L1, int L2, int M, int M1, int M1HI, int LS, int HI>
__device__ __forceinline__ void terms_m1(const ull* A2r, const ull* A2i,
                                         const ull* B2, const ull* BN2,
                                         float* accr, float* acci) {
    if constexpr (M1 <= M1HI) {
        ull t, p;
        mul2(t, A2i[M1 + L1], BN2[M - M1 + L2]);     // (ai*-bi, ai*br)
        fma2p(p, A2r[M1 + L1], B2[M - M1 + L2], t);  // (pr, pi)
        float pr, pi;
        unpack2(pr, pi, p);
        acc_L<L1, L2, M, M1, LS, HI, LS>(pr, pi, accr, acci);
        terms_m1<L1, L2, M, M1 + 1, M1HI, LS, HI>(A2r, A2i, B2, BN2, accr, acci);
    }
}

// scatter finished (L,M) accumulators into the all-L smem image
template <int L1, int L2, int M, int LS, int HI, int L>
__device__ __forceinline__ void st_acc(const float* accr, const float* acci,
                                       float* img, int warp, int lane) {
    if constexpr (L <= HI) {
        constexpr int TW = 2 * L + 1;
        constexpr int PR = pref_region(L1, L2, L);
        float2* dst = (float2*)(img + PR) + warp * (32 * TW) + lane * TW + (M + L);
        *dst = make_float2(accr[L - LS], acci[L - LS]);
        st_acc<L1, L2, M, LS, HI, L + 1>(accr, acci, img, warp, lane);
    }
}

template <int L1, int L2, int M>
__device__ __forceinline__ void do_M(const ull* A2r, const ull* A2i,
                                     const ull* B2, const ull* BN2,
                                     float* img, int warp, int lane) {
    constexpr int LO = (L1 > L2) ? (L1 - L2) : (L2 - L1);
    constexpr int HI = (L1 + L2 < LMAXV) ? (L1 + L2) : LMAXV;
    constexpr int AM = (M < 0) ? -M : M;
    constexpr int LS = (AM > LO) ? AM : LO;
    if constexpr (LS <= HI) {
        constexpr int NL = HI - LS + 1;
        float accr[NL], acci[NL];
#pragma unroll
        for (int i = 0; i < NL; ++i) { accr[i] = 0.f; acci[i] = 0.f; }
        constexpr int M1LO = ((-L1) > (M - L2)) ? (-L1) : (M - L2);
        constexpr int M1HI = (L1 < (M + L2)) ? L1 : (M + L2);
        terms_m1<L1, L2, M, M1LO, M1HI, LS, HI>(A2r, A2i, B2, BN2, accr, acci);
        st_acc<L1, L2, M, LS, HI, LS>(accr, acci, img, warp, lane);
    }
}

template <int L1, int L2, int M, int MHI>
__device__ __forceinline__ void all_M(const ull* A2r, const ull* A2i,
                                      const ull* B2, const ull* BN2,
                                      float* img, int warp, int lane) {
    if constexpr (M <= MHI) {
        do_M<L1, L2, M>(A2r, A2i, B2, BN2, img, warp, lane);
        all_M<L1, L2, M + 1, MHI>(A2r, A2i, B2, BN2, img, warp, lane);
    }
}

// issue one bulk TMA store per L region of the image
template <int L1, int L2, int L>
__device__ __forceinline__ void bulk_L(float* img, float* outb, int tbase) {
    constexpr int HI = (L1 + L2 < LMAXV) ? (L1 + L2) : LMAXV;
    if constexpr (L <= HI) {
        constexpr int TW = 2 * L + 1;
        constexpr int PR = pref_region(L1, L2, L);
        constexpr int OB = out_base_f(L1, L2, L);
        float* g = outb + OB + tbase * (64 * TW);
        unsigned sa = (unsigned)__cvta_generic_to_shared(img + PR);
        asm volatile("cp.async.bulk.global.shared::cta.bulk_group [%0],[%1],%2;"
                     :: "l"(g), "r"(sa), "r"(1024 * TW) : "memory");
        bulk_L<L1, L2, L + 1>(img, outb, tbase);
    }
}

// ---------------- per-pair block body (nIter t1 groups from it0) ------------

template <int L1, int L2>
__device__ __forceinline__ void block_work(const float* __restrict__ fs,
                                           float* __restrict__ out,
                                           float* s1, float* s2, float* simg,
                                           int b, int it0, int nIter) {
    const int tid = threadIdx.x;
    const int warp = tid >> 5;
    const int lane = tid & 31;
    constexpr int LO = (L1 > L2) ? (L1 - L2) : (L2 - L1);
    constexpr int HI = (L1 + L2 < LMAXV) ? (L1 + L2) : LMAXV;

    // stage input fragments (each is 32*(2l+1) float2, contiguous in gmem)
    {
        const float4* i1 = (const float4*)(fs + (size_t)b * 2304 + 64 * L1 * L1);
        const float4* i2 = (const float4*)(fs + (size_t)b * 2304 + 64 * L2 * L2);
        constexpr int N1 = 16 * (2 * L1 + 1);
        constexpr int N2 = 16 * (2 * L2 + 1);
#pragma unroll
        for (int j = tid; j < N1; j += 128) ((float4*)s1)[j] = i1[j];
#pragma unroll
        for (int j = tid; j < N2; j += 128) ((float4*)s2)[j] = i2[j];
    }
    __syncthreads();

    // B side (per lane = t2): natural packs (br,bi) + swapped-neg packs (-bi,br)
    ull B2[2 * L2 + 1], BN2[2 * L2 + 1];
    {
        const ull* bv = (const ull*)s2 + lane * (2 * L2 + 1);
#pragma unroll
        for (int i = 0; i < 2 * L2 + 1; ++i) {
            B2[i] = bv[i];
            float br, bi;
            unpack2(br, bi, B2[i]);
            pack2(BN2[i], -bi, br);
        }
    }

    float* outb = out + (size_t)b * ROWF;
    const int itEnd = it0 + nIter;

#pragma unroll 1
    for (int iter = it0; iter < itEnd; ++iter) {
        const int t1 = iter * 4 + warp;

        // A side: dup packs (ar,ar) and (ai,ai) per m1
        ull A2r[2 * L1 + 1], A2i[2 * L1 + 1];
        {
            const ull* av = (const ull*)s1 + t1 * (2 * L1 + 1);
#pragma unroll
            for (int i = 0; i < 2 * L1 + 1; ++i) {
                float ar, ai;
                ull a = av[i];
                unpack2(ar, ai, a);
                pack2(A2r[i], ar, ar);
                pack2(A2i[i], ai, ai);
            }
        }

        // acquire image: previous iter's TMA smem READS must be done (cheap —
        // does not wait for DRAM completion)
        if (tid == 0)
            asm volatile("cp.async.bulk.wait_group.read 0;" ::: "memory");
        __syncthreads();

        all_M<L1, L2, -HI, HI>(A2r, A2i, B2, BN2, simg, warp, lane);

        // make generic-proxy STS visible to the async (TMA) proxy
        asm volatile("fence.proxy.async.shared::cta;" ::: "memory");
        __syncthreads();

        if (tid == 0) {
            bulk_L<L1, L2, LO>(simg, outb, iter * 4);
            asm volatile("cp.async.bulk.commit_group;" ::: "memory");
        }
    }

    // drain: all bulk stores must complete before the block exits (smem dies)
    if (tid == 0)
        asm volatile("cp.async.bulk.wait_group 0;" ::: "memory");
    __syncthreads();
}

// ---------------- kernel ----------------

// heavy pairs (products >= 77), LPT order: p = l1*6+l2
__device__ __constant__ int HEAVY_ORDER[6] = { 35, 29, 34, 28, 23, 33 };
// remaining 30 pairs, LPT order
__device__ __constant__ int LIGHT_ORDER[30] = {
    22, 27, 17, 32, 21, 16, 26, 15, 20, 11,
    31, 10, 25, 14,  9, 19,  8, 13,  5, 30,
     4, 24,  7,  3, 18,  2, 12,  1,  6,  0
};

__global__ void __launch_bounds__(128, 5)
cg_sparse_kernel(const float* __restrict__ fs, float* __restrict__ out) {
    __shared__ __align__(16) float s1[704];
    __shared__ __align__(16) float s2[704];
    __shared__ __align__(16) float simg[IMG_F];

    const int bx = blockIdx.x;
    int p, b, it0, nIter;
    if (bx < 384) {                    // heavy tier: half-blocks, 4 iters
        p = HEAVY_ORDER[bx >> 6];
        const int j = bx & 63;
        b = j >> 1;
        it0 = (j & 1) * 4;
        nIter = 4;
    } else {                           // light tier: full blocks, 8 iters
        const int j = bx - 384;
        p = LIGHT_ORDER[j >> 5];
        b = j & 31;
        it0 = 0;
        nIter = 8;
    }

#define PCASE(P, A_, B_) case P: block_work<A_, B_>(fs, out, s1, s2, simg, b, it0, nIter); break;
    switch (p) {
        PCASE(0, 0, 0)  PCASE(1, 0, 1)  PCASE(2, 0, 2)  PCASE(3, 0, 3)  PCASE(4, 0, 4)  PCASE(5, 0, 5)
        PCASE(6, 1, 0)  PCASE(7, 1, 1)  PCASE(8, 1, 2)  PCASE(9, 1, 3)  PCASE(10, 1, 4) PCASE(11, 1, 5)
        PCASE(12, 2, 0) PCASE(13, 2, 1) PCASE(14, 2, 2) PCASE(15, 2, 3) PCASE(16, 2, 4) PCASE(17, 2, 5)
        PCASE(18, 3, 0) PCASE(19, 3, 1) PCASE(20, 3, 2) PCASE(21, 3, 3) PCASE(22, 3, 4) PCASE(23, 3, 5)
        PCASE(24, 4, 0) PCASE(25, 4, 1) PCASE(26, 4, 2) PCASE(27, 4, 3) PCASE(28, 4, 4) PCASE(29, 4, 5)
        PCASE(30, 5, 0) PCASE(31, 5, 1) PCASE(32, 5, 2) PCASE(33, 5, 3) PCASE(34, 5, 4) PCASE(35, 5, 5)
        default: break;
    }
#undef PCASE
}

extern "C" void kernel_launch(void* const* d_in, const int* in_sizes, int n_in,
                              void* d_out, int out_size) {
    const float* fs = (const float*)d_in[0];
    float* out = (float*)d_out;
    cg_sparse_kernel<<<NBLOCKS, 128>>>(fs, out);
}